// round 7
// baseline (speedup 1.0000x reference)
#include <cuda_runtime.h>
#include <math.h>

// RoPE: out[..., 2i]   = cos(a)*x[...,2i] - sin(a)*x[...,2i+1]
//       out[..., 2i+1] = sin(a)*x[...,2i] + cos(a)*x[...,2i+1]
// a = pos * 10000^(-i/32),  D_K=64, pos in [0, 4096)
//
// Strategy: 1 MiB cos/sin lookup table (4096 pos x 32 freqs, float2) built in
// double precision, then a pure float4-streaming main kernel.
// Positions dtype (int32 vs int64 in the harness buffer) is detected at
// runtime by a 1-thread kernel, since the harness may narrow int64 -> int32.

#define HALF 32            // D_K / 2
#define MAX_POS 4096

__device__ float2 g_rope_table[MAX_POS * HALF];   // cos in .x, sin in .y, [pos][freq]
__device__ int    g_pos_is_i64;                   // 1 if positions are 8-byte ints

__global__ void detect_pos_dtype_kernel(const int* __restrict__ posw) {
    // If dtype is int64 with values < 2^32, every odd 32-bit word is 0.
    // If dtype is int32 (sorted random in [0,4096)), 32 consecutive zero
    // odd-words is effectively impossible.
    int i64 = 1;
    #pragma unroll
    for (int k = 0; k < 32; k++) {
        if (posw[2 * k + 1] != 0) { i64 = 0; break; }
    }
    g_pos_is_i64 = i64;
}

__global__ void build_table_kernel() {
    int idx = blockIdx.x * blockDim.x + threadIdx.x;
    if (idx >= MAX_POS * HALF) return;
    int p = idx >> 5;       // position
    int i = idx & 31;       // frequency index
    double lf = log(10000.0);
    float inv_freq = (float)exp(-((double)i / 32.0) * lf);  // fp32-rounded, like ref
    float angle = (float)p * inv_freq;                      // fp32 product, like ref
    double s, c;
    sincos((double)angle, &s, &c);                          // accurate sin/cos of fp32 angle
    g_rope_table[idx] = make_float2((float)c, (float)s);
}

__global__ void __launch_bounds__(256) rope_kernel(
    const float4* __restrict__ x,
    const int*    __restrict__ posw,   // raw 32-bit view of positions buffer
    float4*       __restrict__ out,
    int n4)
{
    int idx = blockIdx.x * blockDim.x + threadIdx.x;
    if (idx >= n4) return;

    int row = idx >> 4;        // 16 float4 per 64-elem row
    int j   = idx & 15;        // which float4 -> table pairs (2j, 2j+1)

    // dtype-agnostic position read (little-endian low word for int64)
    int p = g_pos_is_i64 ? __ldg(&posw[2 * row]) : __ldg(&posw[row]);
    p = min(max(p, 0), MAX_POS - 1);             // defensive clamp: no OOB ever

    float4 xv = __ldg(&x[idx]);                  // (x1e, x1o, x2e, x2o)

    const float4* tp = reinterpret_cast<const float4*>(&g_rope_table[p * HALF + 2 * j]);
    float4 t = __ldg(tp);                        // (cos0, sin0, cos1, sin1)

    float4 o;
    o.x = fmaf(t.x, xv.x, -t.y * xv.y);          // cos*x1 - sin*x2
    o.y = fmaf(t.y, xv.x,  t.x * xv.y);          // sin*x1 + cos*x2
    o.z = fmaf(t.z, xv.z, -t.w * xv.w);
    o.w = fmaf(t.w, xv.z,  t.z * xv.w);

    out[idx] = o;
}

extern "C" void kernel_launch(void* const* d_in, const int* in_sizes, int n_in,
                              void* d_out, int out_size) {
    const float4* x    = (const float4*)d_in[0];
    const int*    posw = (const int*)d_in[1];    // raw word view; dtype detected on device
    float4*       out  = (float4*)d_out;

    int n  = in_sizes[0];          // 8*16*4096*64 = 33,554,432
    int n4 = n >> 2;               // float4 count

    detect_pos_dtype_kernel<<<1, 1>>>(posw);
    build_table_kernel<<<(MAX_POS * HALF + 511) / 512, 512>>>();

    int threads = 256;
    int blocks = (n4 + threads - 1) / threads;
    rope_kernel<<<blocks, threads>>>(x, posw, out, n4);
}

// round 8
// speedup vs baseline: 1.2306x; 1.2306x over previous
#include <cuda_runtime.h>
#include <math.h>

// RoPE: out[..., 2i]   = cos(a)*x[...,2i] - sin(a)*x[...,2i+1]
//       out[..., 2i+1] = sin(a)*x[...,2i] + cos(a)*x[...,2i+1]
// a = pos * 10000^(-i/32),  D_K=64, pos in [0, 4096)
//
// 1 MiB cos/sin table (4096 pos x 32 freqs, float2), rebuilt each call
// (deterministic). Setup kernel also detects positions dtype (int32 vs int64
// harness buffer) in thread 0. Main kernel: 2x float4 stream per thread with
// streaming cache hints; table reads hit L1/L2 (positions are sorted).

#define HALF 32            // D_K / 2
#define MAX_POS 4096

__device__ float2 g_rope_table[MAX_POS * HALF];   // cos in .x, sin in .y, [pos][freq]
__device__ int    g_pos_is_i64;                   // 1 if positions are 8-byte ints

__global__ void setup_kernel(const int* __restrict__ posw) {
    int idx = blockIdx.x * blockDim.x + threadIdx.x;

    // thread 0: dtype detection. int64 values < 2^32 -> every odd word is 0.
    // int32 sorted-random in [0,4096): 32 consecutive zero odd-words ~impossible.
    if (idx == 0) {
        int i64 = 1;
        #pragma unroll
        for (int k = 0; k < 32; k++)
            if (posw[2 * k + 1] != 0) { i64 = 0; break; }
        g_pos_is_i64 = i64;
    }

    if (idx >= MAX_POS * HALF) return;
    int p = idx >> 5;       // position
    int i = idx & 31;       // frequency index
    // inv_freq rounded to fp32 (matches reference's fp32 theta**(-2i/64))
    float inv_freq = (float)exp(-((double)i / 32.0) * log(10000.0));
    float angle = (float)p * inv_freq;              // fp32 product, like ref
    float s, c;
    sincosf(angle, &s, &c);                          // accurate fp32 sincos
    g_rope_table[idx] = make_float2(c, s);
}

__global__ void __launch_bounds__(256) rope_kernel(
    const float4* __restrict__ x,
    const int*    __restrict__ posw,   // raw 32-bit view of positions buffer
    float4*       __restrict__ out,
    int n8)                            // number of float4-PAIRS
{
    int t = blockIdx.x * blockDim.x + threadIdx.x;
    if (t >= n8) return;

    int idx = t << 1;          // first float4 index of this thread's pair
    int row = idx >> 4;        // 16 float4 per 64-elem row
    int j   = idx & 15;        // even: this thread covers table pairs 2j..2j+3

    // dtype-agnostic position read (LE low word for int64); uniform branch
    int p = g_pos_is_i64 ? __ldg(&posw[2 * row]) : __ldg(&posw[row]);
    p = min(max(p, 0), MAX_POS - 1);               // defensive clamp: no OOB ever

    // streaming loads: x is touched exactly once
    float4 xa = __ldcs(&x[idx]);
    float4 xb = __ldcs(&x[idx + 1]);

    // table: default caching, stays L1/L2 resident
    const float4* tp = reinterpret_cast<const float4*>(&g_rope_table[p * HALF + 2 * j]);
    float4 ta = __ldg(tp);                          // (cos0, sin0, cos1, sin1)
    float4 tb = __ldg(tp + 1);                      // (cos2, sin2, cos3, sin3)

    float4 oa, ob;
    oa.x = fmaf(ta.x, xa.x, -ta.y * xa.y);
    oa.y = fmaf(ta.y, xa.x,  ta.x * xa.y);
    oa.z = fmaf(ta.z, xa.z, -ta.w * xa.w);
    oa.w = fmaf(ta.w, xa.z,  ta.z * xa.w);
    ob.x = fmaf(tb.x, xb.x, -tb.y * xb.y);
    ob.y = fmaf(tb.y, xb.x,  tb.x * xb.y);
    ob.z = fmaf(tb.z, xb.z, -tb.w * xb.w);
    ob.w = fmaf(tb.w, xb.z,  tb.z * xb.w);

    // streaming stores: out is never re-read by this kernel
    __stcs(&out[idx],     oa);
    __stcs(&out[idx + 1], ob);
}

extern "C" void kernel_launch(void* const* d_in, const int* in_sizes, int n_in,
                              void* d_out, int out_size) {
    const float4* x    = (const float4*)d_in[0];
    const int*    posw = (const int*)d_in[1];    // raw word view; dtype detected on device
    float4*       out  = (float4*)d_out;

    int n  = in_sizes[0];          // 8*16*4096*64 = 33,554,432
    int n8 = n >> 3;               // float4 pairs = 4,194,304

    setup_kernel<<<(MAX_POS * HALF + 511) / 512, 512>>>(posw);

    int threads = 256;
    int blocks = (n8 + threads - 1) / threads;   // 16384
    rope_kernel<<<blocks, threads>>>(x, posw, out, n8);
}